// round 1
// baseline (speedup 1.0000x reference)
#include <cuda_runtime.h>
#include <stdint.h>

// SoftALU: inputs are exact one-hot [B,4,256]; with SHARP=100 the reference
// output is (to within ~e^-100, i.e. fp32 denormals) the exact one-hot
// encoding of the 7 uint32 results: add, sub, mul, div, and, or, xor.
// So: decode bytes via argmax (value > 0.5), do integer ALU, re-encode.
//
// One block per batch element. 256 threads.
//   Loads : 2 inputs x 4 bytes x 64 float4 = 512 float4 -> 2 per thread.
//   Stores: 7 ops x 1024 floats = 7 x 256 float4 -> 7 per thread (coalesced).
__global__ void __launch_bounds__(256) softalu_kernel(
    const float* __restrict__ a,
    const float* __restrict__ b,
    float* __restrict__ out,
    int batch_count)
{
    const int batch = blockIdx.x;
    const int tid   = threadIdx.x;

    __shared__ int sbyte[2][4];

    const float4* a4 = reinterpret_cast<const float4*>(a) + (size_t)batch * 256;
    const float4* b4 = reinterpret_cast<const float4*>(b) + (size_t)batch * 256;

    // Locate the 1.0 in each of the 8 one-hot rows (exactly one thread/lane hits per row).
    #pragma unroll
    for (int k = tid; k < 512; k += 256) {
        const int which = k >> 8;        // 0 = a, 1 = b
        const int rest  = k & 255;       // 0..255: (byte n)*64 + q
        const int n     = rest >> 6;     // byte index 0..3 (LSB first)
        const int q     = rest & 63;     // float4 index within the 256-wide row
        const float4 v  = (which ? b4 : a4)[rest];
        if (v.x > 0.5f) sbyte[which][n] = q * 4 + 0;
        if (v.y > 0.5f) sbyte[which][n] = q * 4 + 1;
        if (v.z > 0.5f) sbyte[which][n] = q * 4 + 2;
        if (v.w > 0.5f) sbyte[which][n] = q * 4 + 3;
    }
    __syncthreads();

    const uint32_t va = (uint32_t)sbyte[0][0]
                      | ((uint32_t)sbyte[0][1] << 8)
                      | ((uint32_t)sbyte[0][2] << 16)
                      | ((uint32_t)sbyte[0][3] << 24);
    const uint32_t vb = (uint32_t)sbyte[1][0]
                      | ((uint32_t)sbyte[1][1] << 8)
                      | ((uint32_t)sbyte[1][2] << 16)
                      | ((uint32_t)sbyte[1][3] << 24);

    uint32_t r[7];
    r[0] = va + vb;                 // soft_add
    r[1] = va - vb;                 // soft_add(a, soft_negate(b)) = a + (~b + 1)
    r[2] = va * vb;                 // soft_mul (wraps mod 2^32, same as jnp uint32)
    r[3] = vb ? (va / vb) : 0u;     // soft_div (div-by-zero -> 0)
    r[4] = va & vb;
    r[5] = va | vb;
    r[6] = va ^ vb;

    // Output layout: [7, B, 4, 256] row-major -> per op a plane of B*256 float4s.
    float4* o4 = reinterpret_cast<float4*>(out);
    const size_t plane = (size_t)batch_count * 256;   // float4s per op
    const int n   = tid >> 6;       // byte slot 0..3
    const int q   = tid & 63;       // float4 within 256-wide row
    const int c0  = q * 4;
    const int sh  = n * 8;

    #pragma unroll
    for (int op = 0; op < 7; op++) {
        const int tgt = (int)((r[op] >> sh) & 255u);
        float4 v;
        v.x = (c0 + 0 == tgt) ? 1.0f : 0.0f;
        v.y = (c0 + 1 == tgt) ? 1.0f : 0.0f;
        v.z = (c0 + 2 == tgt) ? 1.0f : 0.0f;
        v.w = (c0 + 3 == tgt) ? 1.0f : 0.0f;
        o4[(size_t)op * plane + (size_t)batch * 256 + tid] = v;
    }
}

extern "C" void kernel_launch(void* const* d_in, const int* in_sizes, int n_in,
                              void* d_out, int out_size)
{
    const float* a = (const float*)d_in[0];
    const float* b = (const float*)d_in[1];
    const int batch = in_sizes[0] / 1024;   // [B,4,256] -> B
    softalu_kernel<<<batch, 256>>>(a, b, (float*)d_out, batch);
}

// round 2
// speedup vs baseline: 1.0064x; 1.0064x over previous
#include <cuda_runtime.h>
#include <stdint.h>

// SoftALU: inputs are exact one-hot [B,4,256]; with SHARP=100 the reference
// output equals (to within fp32 denormals) the exact one-hot encoding of the
// 7 uint32 results: add, sub, mul, div, and, or, xor.
//
// Pure HBM-bound: 64MB read + 235MB write, zero real compute.
// R2: streaming loads/stores (.cs, evict-first) to stop the 235MB write
// stream from thrashing L2 against the 64MB read stream.
__global__ void __launch_bounds__(256) softalu_kernel(
    const float* __restrict__ a,
    const float* __restrict__ b,
    float* __restrict__ out,
    int batch_count)
{
    const int batch = blockIdx.x;
    const int tid   = threadIdx.x;

    __shared__ int sbyte[2][4];

    const float4* a4 = reinterpret_cast<const float4*>(a) + (size_t)batch * 256;
    const float4* b4 = reinterpret_cast<const float4*>(b) + (size_t)batch * 256;

    // Locate the 1.0 in each of the 8 one-hot rows.
    // k in [0,512): which input (a/b), byte slot n (0..3), float4 q (0..63).
    #pragma unroll
    for (int k = tid; k < 512; k += 256) {
        const int which = k >> 8;
        const int rest  = k & 255;
        const int n     = rest >> 6;
        const int q     = rest & 63;
        const float4 v  = __ldcs((which ? b4 : a4) + rest);   // streaming load
        if (v.x > 0.5f) sbyte[which][n] = q * 4 + 0;
        if (v.y > 0.5f) sbyte[which][n] = q * 4 + 1;
        if (v.z > 0.5f) sbyte[which][n] = q * 4 + 2;
        if (v.w > 0.5f) sbyte[which][n] = q * 4 + 3;
    }
    __syncthreads();

    const uint32_t va = (uint32_t)sbyte[0][0]
                      | ((uint32_t)sbyte[0][1] << 8)
                      | ((uint32_t)sbyte[0][2] << 16)
                      | ((uint32_t)sbyte[0][3] << 24);
    const uint32_t vb = (uint32_t)sbyte[1][0]
                      | ((uint32_t)sbyte[1][1] << 8)
                      | ((uint32_t)sbyte[1][2] << 16)
                      | ((uint32_t)sbyte[1][3] << 24);

    uint32_t r[7];
    r[0] = va + vb;                 // add
    r[1] = va - vb;                 // a + (~b + 1)
    r[2] = va * vb;                 // mul (mod 2^32)
    r[3] = vb ? (va / vb) : 0u;     // div (div-by-zero -> 0)
    r[4] = va & vb;
    r[5] = va | vb;
    r[6] = va ^ vb;

    // Output [7, B, 4, 256]: per op a plane of B*256 float4s; this block's
    // slice of each plane is 256 consecutive float4s (4KB, fully coalesced).
    float4* o4 = reinterpret_cast<float4*>(out);
    const size_t plane = (size_t)batch_count * 256;
    const size_t base  = (size_t)batch * 256 + tid;
    const int n   = tid >> 6;
    const int c0  = (tid & 63) * 4;
    const int sh  = n * 8;

    #pragma unroll
    for (int op = 0; op < 7; op++) {
        const int tgt = (int)((r[op] >> sh) & 255u);
        float4 v;
        v.x = (c0 + 0 == tgt) ? 1.0f : 0.0f;
        v.y = (c0 + 1 == tgt) ? 1.0f : 0.0f;
        v.z = (c0 + 2 == tgt) ? 1.0f : 0.0f;
        v.w = (c0 + 3 == tgt) ? 1.0f : 0.0f;
        __stcs(o4 + (size_t)op * plane + base, v);            // streaming store
    }
}

extern "C" void kernel_launch(void* const* d_in, const int* in_sizes, int n_in,
                              void* d_out, int out_size)
{
    const float* a = (const float*)d_in[0];
    const float* b = (const float*)d_in[1];
    const int batch = in_sizes[0] / 1024;   // [B,4,256] -> B
    softalu_kernel<<<batch, 256>>>(a, b, (float*)d_out, batch);
}